// round 9
// baseline (speedup 1.0000x reference)
#include <cuda_runtime.h>

// IAF spiking layer forward; vmem matches XLA ReduceWindowRewriter's scan
// association (base_length = 16) for cumsum over T=512 — verified bitwise
// (R8: rel_err == 0.0).
//
//   i = 16k + c,  k = 16s + r
//   I[i]   = sequential prefix of x within block k        (leading 0 exact)
//   SPin_k = sequential prefix of block totals within superblock s
//   C_k    = add(ET_s, SPin_k), ET_s in {0, U0}
//   vmem[i] = add(C_{k-1}, I[i])
//   s_t = ((vmem_t - sub) - 1.0 >= 0);  sub += s_t   (sub integer-exact)
//
// R9: float4 vectorization — one thread owns 4 adjacent features.
// Per-lane arithmetic order is unchanged (features independent), so results
// stay bitwise identical. 512B/warp per LDG/STG, 16 front-batched vector
// loads per unrolled block => ~56KB/SM in flight, DRAM latency fully hidden.

#define T_SIM 512
#define FEAT  8192
#define VFEAT (FEAT / 4)   // 2048 float4 lanes per row

__global__ __launch_bounds__(128)
void iaf_kernel(const float4* __restrict__ x, float4* __restrict__ out)
{
    const int vf = blockIdx.x * blockDim.x + threadIdx.x;  // float4 feature idx
    const int b  = blockIdx.y;

    const long long base = (long long)b * T_SIM * VFEAT + vf;
    const float4* __restrict__ xp = x + base;
    float4* __restrict__ op = out + base;

    // per-lane state (4 independent sequences)
    float E0 = 0.f, E1 = 0.f, E2 = 0.f, E3 = 0.f;      // exclusive block prefix
    float ET0 = 0.f, ET1 = 0.f, ET2 = 0.f, ET3 = 0.f;  // exclusive top prefix
    float SP0 = 0.f, SP1 = 0.f, SP2 = 0.f, SP3 = 0.f;  // superblock fold
    float sb0 = 0.f, sb1 = 0.f, sb2 = 0.f, sb3 = 0.f;  // membrane subtraction

    for (int k = 0; k < 32; ++k) {                     // 32 blocks of 16 steps
        const float4* __restrict__ xb = xp + (long long)k * 16 * VFEAT;
        float4* __restrict__ ob = op + (long long)k * 16 * VFEAT;

        float I0 = 0.f, I1 = 0.f, I2 = 0.f, I3 = 0.f;  // in-block prefix

        #pragma unroll
        for (int c = 0; c < 16; ++c) {
            float4 xv = __ldcs(xb + (long long)c * VFEAT);

            I0 = I0 + xv.x;  I1 = I1 + xv.y;
            I2 = I2 + xv.z;  I3 = I3 + xv.w;

            float v0 = E0 + I0, v1 = E1 + I1, v2 = E2 + I2, v3 = E3 + I3;

            float u0 = (v0 - sb0) - 1.0f;
            float u1 = (v1 - sb1) - 1.0f;
            float u2 = (v2 - sb2) - 1.0f;
            float u3 = (v3 - sb3) - 1.0f;

            float4 sv;
            sv.x = (u0 >= 0.0f) ? 1.0f : 0.0f;
            sv.y = (u1 >= 0.0f) ? 1.0f : 0.0f;
            sv.z = (u2 >= 0.0f) ? 1.0f : 0.0f;
            sv.w = (u3 >= 0.0f) ? 1.0f : 0.0f;

            sb0 += sv.x;  sb1 += sv.y;  sb2 += sv.z;  sb3 += sv.w;

            __stcs(ob + (long long)c * VFEAT, sv);
        }

        // block boundary: T_k = I; fold into superblock prefix
        SP0 = SP0 + I0;  SP1 = SP1 + I1;  SP2 = SP2 + I2;  SP3 = SP3 + I3;

        if (k == 15) {
            ET0 = SP0; ET1 = SP1; ET2 = SP2; ET3 = SP3;  // U0 = C_15
            E0 = ET0;  E1 = ET1;  E2 = ET2;  E3 = ET3;
            SP0 = SP1 = SP2 = SP3 = 0.0f;
        } else {
            E0 = ET0 + SP0;  E1 = ET1 + SP1;
            E2 = ET2 + SP2;  E3 = ET3 + SP3;
        }
    }
}

extern "C" void kernel_launch(void* const* d_in, const int* in_sizes, int n_in,
                              void* d_out, int out_size)
{
    const float4* x = (const float4*)d_in[0];
    float4* out = (float4*)d_out;

    int total = in_sizes[0];
    int batch = total / (T_SIM * FEAT);

    dim3 block(128, 1, 1);
    dim3 grid(VFEAT / 128, batch, 1);   // 16 x batch blocks
    iaf_kernel<<<grid, block>>>(x, out);
}

// round 10
// speedup vs baseline: 3.1338x; 3.1338x over previous
#include <cuda_runtime.h>

// IAF spiking layer forward; vmem matches XLA ReduceWindowRewriter's scan
// association (base_length = 16) for cumsum over T=512 — verified bitwise
// (R8: rel_err == 0.0). Arithmetic order identical to R8; only memory
// scheduling changed.
//
//   i = 16k + c,  k = 16s + r
//   I[i]   = sequential prefix of x within block k        (leading 0 exact)
//   SPin_k = sequential prefix of block totals within superblock s
//   C_k    = add(ET_s, SPin_k), ET_s in {0, U0}
//   vmem[i] = add(C_{k-1}, I[i])
//   s_t = ((vmem_t - sub) - 1.0 >= 0);  sub += s_t   (sub integer-exact)
//
// R10: scalar one-thread-per-(b,f) (full TLP, 27.7 warps/SM) + EXPLICIT
// 16-deep load batching per block: all 16 timestep loads hoisted into regs
// before the serial spike chain -> MLP_p1 = 16 -> ~56KB/SM in flight.
// Streaming cache hints (.cs) on both load and store (zero reuse).

#define T_SIM 512
#define FEAT  8192

__global__ __launch_bounds__(256)
void iaf_kernel(const float* __restrict__ x, float* __restrict__ out)
{
    const int f = blockIdx.x * blockDim.x + threadIdx.x;
    const int b = blockIdx.y;

    const long long base = (long long)b * T_SIM * FEAT + f;
    const float* __restrict__ xp = x + base;
    float* __restrict__ op = out + base;

    float E    = 0.0f;   // exclusive block prefix (C_{k-1})
    float ET   = 0.0f;   // exclusive superblock prefix (0, then U0)
    float SPin = 0.0f;   // sequential fold of block totals in superblock
    float sub  = 0.0f;   // accumulated membrane subtraction (integer-exact)

    for (int k = 0; k < 32; ++k) {               // 32 blocks of 16 timesteps
        const float* __restrict__ xb = xp + (long long)k * 16 * FEAT;
        float* __restrict__ ob = op + (long long)k * 16 * FEAT;

        // ---- batched loads: 16 independent LDGs issued back-to-back ----
        float xv[16];
        #pragma unroll
        for (int c = 0; c < 16; ++c)
            xv[c] = __ldcs(xb + c * FEAT);

        // ---- serial spike chain (identical fp order to R8) ----
        float I = 0.0f;
        #pragma unroll
        for (int c = 0; c < 16; ++c) {
            I = I + xv[c];                       // leading 0+x exact
            float v = E + I;
            float u = (v - sub) - 1.0f;
            float s = (u >= 0.0f) ? 1.0f : 0.0f;
            sub += s;
            __stcs(ob + c * FEAT, s);
        }

        // block boundary: T_k = I
        SPin = SPin + I;
        if (k == 15) {
            ET   = SPin;                         // U0 = C_15
            E    = ET;
            SPin = 0.0f;
        } else {
            E = ET + SPin;                       // C_k = add(ET, SPin)
        }
    }
}

extern "C" void kernel_launch(void* const* d_in, const int* in_sizes, int n_in,
                              void* d_out, int out_size)
{
    const float* x = (const float*)d_in[0];
    float* out = (float*)d_out;

    int total = in_sizes[0];
    int batch = total / (T_SIM * FEAT);

    dim3 block(256, 1, 1);
    dim3 grid(FEAT / 256, batch, 1);             // 32 x 16 = 512 blocks
    iaf_kernel<<<grid, block>>>(x, out);
}